// round 1
// baseline (speedup 1.0000x reference)
#include <cuda_runtime.h>
#include <math.h>

#define NNODES 100000
#define NEDGES 1600000

// ---------------- scratch (device globals; no runtime allocation) ----------------
__device__ __align__(128) float g_feat[NNODES * 128];  // normalized layer output
__device__ __align__(128) float g_h[NNODES * 128];     // post-GEMM features
__device__ float g_als[NNODES * 4];
__device__ float g_ald[NNODES * 4];
__device__ int   g_deg[NNODES];
__device__ int   g_off[NNODES + 1];
__device__ int   g_cur[NNODES];
__device__ int   g_bsum[256];
__device__ int   g_csr[NEDGES];

// ---------------- CSR build ----------------
__global__ void zero_deg_kernel(int n) {
    int i = blockIdx.x * blockDim.x + threadIdx.x;
    if (i < n) g_deg[i] = 0;
}

__global__ void count_kernel(const int* __restrict__ ei, int e) {
    int i = blockIdx.x * blockDim.x + threadIdx.x;
    if (i < e) atomicAdd(&g_deg[ei[e + i]], 1);
}

__global__ void scan1_kernel(int n) {
    __shared__ int sm[1024];
    int i = blockIdx.x * 1024 + threadIdx.x;
    int v = (i < n) ? g_deg[i] : 0;
    sm[threadIdx.x] = v;
    __syncthreads();
    #pragma unroll
    for (int d = 1; d < 1024; d <<= 1) {
        int t = (threadIdx.x >= d) ? sm[threadIdx.x - d] : 0;
        __syncthreads();
        sm[threadIdx.x] += t;
        __syncthreads();
    }
    if (i < n) g_off[i] = sm[threadIdx.x] - v;   // exclusive
    if (threadIdx.x == 1023) g_bsum[blockIdx.x] = sm[1023];
}

__global__ void scan2_kernel(int nb) {
    if (threadIdx.x == 0) {
        int run = 0;
        for (int i = 0; i < nb; i++) { int t = g_bsum[i]; g_bsum[i] = run; run += t; }
    }
}

__global__ void scan3_kernel(int n, int e) {
    int i = blockIdx.x * 1024 + threadIdx.x;
    if (i < n) {
        int o = g_off[i] + g_bsum[blockIdx.x];
        g_off[i] = o;
        g_cur[i] = o;
    }
    if (i == 0) g_off[n] = e;
}

__global__ void fill_kernel(const int* __restrict__ ei, int e) {
    int i = blockIdx.x * blockDim.x + threadIdx.x;
    if (i < e) {
        int src = ei[i];
        int dst = ei[e + i];
        int pos = atomicAdd(&g_cur[dst], 1);
        g_csr[pos] = src;
    }
}

// ---------------- GEMM: H[n,FOUT] = A[n,FIN] @ W[FIN,FOUT] ----------------
// Warp per row; full W staged in shared memory.
template <int FIN, int FOUT>
__global__ __launch_bounds__(256) void gemm_kernel(const float* __restrict__ A,
                                                   const float* __restrict__ W,
                                                   float* __restrict__ H, int n) {
    extern __shared__ float Wsm[];
    for (int i = threadIdx.x; i < FIN * FOUT; i += 256) Wsm[i] = W[i];
    __syncthreads();
    int row = blockIdx.x * 8 + (threadIdx.x >> 5);
    if (row >= n) return;
    int lane = threadIdx.x & 31;
    float a[FIN / 32];
    #pragma unroll
    for (int j = 0; j < FIN / 32; j++) a[j] = A[(size_t)row * FIN + j * 32 + lane];

    if (FOUT == 128) {
        float4 acc = make_float4(0.f, 0.f, 0.f, 0.f);
        #pragma unroll
        for (int k = 0; k < FIN; k++) {
            float ak = __shfl_sync(0xffffffffu, a[k >> 5], k & 31);
            float4 w4 = *(const float4*)&Wsm[k * FOUT + lane * 4];
            acc.x += ak * w4.x; acc.y += ak * w4.y;
            acc.z += ak * w4.z; acc.w += ak * w4.w;
        }
        *(float4*)&H[(size_t)row * FOUT + lane * 4] = acc;
    } else {  // FOUT == 32
        float acc = 0.f;
        #pragma unroll
        for (int k = 0; k < FIN; k++) {
            float ak = __shfl_sync(0xffffffffu, a[k >> 5], k & 31);
            acc += ak * Wsm[k * FOUT + lane];
        }
        H[(size_t)row * FOUT + lane] = acc;
    }
}

// ---------------- attention logits: al[n,heads] = <h[n,head,:], a[head,:]> ----------------
__global__ void al_kernel(const float* __restrict__ H, const float* __restrict__ asrc,
                          const float* __restrict__ adst, float* __restrict__ als,
                          float* __restrict__ ald, int n, int heads) {
    int i = blockIdx.x * blockDim.x + threadIdx.x;
    if (i >= n * heads) return;
    int node = i / heads;
    int head = i - node * heads;
    const float* hp = H + (size_t)node * heads * 32 + head * 32;
    float s1 = 0.f, s2 = 0.f;
    #pragma unroll
    for (int c = 0; c < 32; c++) {
        float hv = hp[c];
        s1 += hv * asrc[head * 32 + c];
        s2 += hv * adst[head * 32 + c];
    }
    als[i] = s1;
    ald[i] = s2;
}

// ---------------- aggregation, 4 heads x 32ch, fused softmax+bias+BN+ELU ----------------
// Warp per destination node; online softmax; lane owns 4 consecutive channels.
__global__ void agg128_kernel(const float* __restrict__ H, const float* __restrict__ als,
                              const float* __restrict__ ald,
                              const float* __restrict__ bias, const float* __restrict__ gamma,
                              const float* __restrict__ beta, const float* __restrict__ mean,
                              const float* __restrict__ var,
                              float* __restrict__ out, int n) {
    int v = (blockIdx.x * blockDim.x + threadIdx.x) >> 5;
    if (v >= n) return;
    int lane = threadIdx.x & 31;
    int head = lane >> 3;
    int c0 = lane * 4;
    float aldv = ald[v * 4 + head];
    int s0 = g_off[v], s1 = g_off[v + 1];
    float m = -INFINITY, s = 0.f;
    float4 acc = make_float4(0.f, 0.f, 0.f, 0.f);
    for (int idx = s0; idx < s1; idx++) {
        int u = g_csr[idx];
        float ee = als[u * 4 + head] + aldv;
        ee = ee > 0.f ? ee : 0.2f * ee;           // leaky relu
        float mn = fmaxf(m, ee);
        float sc = __expf(m - mn);                 // 0 when m == -inf
        float wt = __expf(ee - mn);
        s = s * sc + wt;
        float4 hv = *(const float4*)&H[(size_t)u * 128 + c0];
        acc.x = acc.x * sc + wt * hv.x;
        acc.y = acc.y * sc + wt * hv.y;
        acc.z = acc.z * sc + wt * hv.z;
        acc.w = acc.w * sc + wt * hv.w;
        m = mn;
    }
    float inv = 1.f / (s + 1e-16f);
    float res[4] = {acc.x * inv, acc.y * inv, acc.z * inv, acc.w * inv};
    #pragma unroll
    for (int j = 0; j < 4; j++) {
        int c = c0 + j;
        float y = res[j] + bias[c];
        y = (y - mean[c]) * rsqrtf(var[c] + 1e-5f) * gamma[c] + beta[c];
        y = y > 0.f ? y : expm1f(y);               // ELU
        out[(size_t)v * 128 + c] = y;
    }
}

// ---------------- layer-2 aggregation (1 head, 32ch) + fused BN+ELU+classifier ----------------
__global__ void agg32_kernel(const float* __restrict__ H, const float* __restrict__ als,
                             const float* __restrict__ ald,
                             const float* __restrict__ bias, const float* __restrict__ gamma,
                             const float* __restrict__ beta, const float* __restrict__ mean,
                             const float* __restrict__ var,
                             const float* __restrict__ Wc, const float* __restrict__ bc,
                             float* __restrict__ out, int n) {
    int v = (blockIdx.x * blockDim.x + threadIdx.x) >> 5;
    if (v >= n) return;
    int lane = threadIdx.x & 31;
    float aldv = ald[v];
    int s0 = g_off[v], s1 = g_off[v + 1];
    float m = -INFINITY, s = 0.f, acc = 0.f;
    for (int idx = s0; idx < s1; idx++) {
        int u = g_csr[idx];
        float ee = als[u] + aldv;
        ee = ee > 0.f ? ee : 0.2f * ee;
        float mn = fmaxf(m, ee);
        float sc = __expf(m - mn);
        float wt = __expf(ee - mn);
        s = s * sc + wt;
        acc = acc * sc + wt * H[(size_t)u * 32 + lane];
        m = mn;
    }
    float y = acc / (s + 1e-16f) + bias[lane];
    y = (y - mean[lane]) * rsqrtf(var[lane] + 1e-5f) * gamma[lane] + beta[lane];
    y = y > 0.f ? y : expm1f(y);
    // classifier: out[v,c] = sum_l y_l * Wc[l,c] + bc[c]
    #pragma unroll
    for (int c = 0; c < 10; c++) {
        float p = y * Wc[lane * 10 + c];
        #pragma unroll
        for (int o = 16; o; o >>= 1) p += __shfl_xor_sync(0xffffffffu, p, o);
        if (lane == 0) out[(size_t)v * 10 + c] = p + bc[c];
    }
}

// ---------------- launch ----------------
extern "C" void kernel_launch(void* const* d_in, const int* in_sizes, int n_in,
                              void* d_out, int out_size) {
    const float* x   = (const float*)d_in[0];
    const int*   ei  = (const int*)d_in[1];
    const float* W0  = (const float*)d_in[2];
    const float* as0 = (const float*)d_in[3];
    const float* ad0 = (const float*)d_in[4];
    const float* b0  = (const float*)d_in[5];
    const float* gm0 = (const float*)d_in[6];
    const float* bt0 = (const float*)d_in[7];
    const float* m0  = (const float*)d_in[8];
    const float* v0  = (const float*)d_in[9];
    const float* W1  = (const float*)d_in[10];
    const float* as1 = (const float*)d_in[11];
    const float* ad1 = (const float*)d_in[12];
    const float* b1  = (const float*)d_in[13];
    const float* gm1 = (const float*)d_in[14];
    const float* bt1 = (const float*)d_in[15];
    const float* m1  = (const float*)d_in[16];
    const float* v1  = (const float*)d_in[17];
    const float* W2  = (const float*)d_in[18];
    const float* as2 = (const float*)d_in[19];
    const float* ad2 = (const float*)d_in[20];
    const float* b2  = (const float*)d_in[21];
    const float* gm2 = (const float*)d_in[22];
    const float* bt2 = (const float*)d_in[23];
    const float* m2  = (const float*)d_in[24];
    const float* v2  = (const float*)d_in[25];
    const float* Wc  = (const float*)d_in[26];
    const float* bc  = (const float*)d_in[27];

    int n = in_sizes[0] / 128;   // 100000
    int e = in_sizes[1] / 2;     // 1600000

    float *feat, *h, *als, *ald;
    cudaGetSymbolAddress((void**)&feat, g_feat);
    cudaGetSymbolAddress((void**)&h, g_h);
    cudaGetSymbolAddress((void**)&als, g_als);
    cudaGetSymbolAddress((void**)&ald, g_ald);

    cudaFuncSetAttribute(gemm_kernel<128, 128>,
                         cudaFuncAttributeMaxDynamicSharedMemorySize, 128 * 128 * 4);

    int nb = (n + 1023) / 1024;
    int eb = (e + 255) / 256;
    int gblocks = (n + 7) / 8;

    // CSR by destination (shared by all 3 layers)
    zero_deg_kernel<<<(n + 255) / 256, 256>>>(n);
    count_kernel<<<eb, 256>>>(ei, e);
    scan1_kernel<<<nb, 1024>>>(n);
    scan2_kernel<<<1, 32>>>(nb);
    scan3_kernel<<<nb, 1024>>>(n, e);
    fill_kernel<<<eb, 256>>>(ei, e);

    // layer 0
    gemm_kernel<128, 128><<<gblocks, 256, 128 * 128 * 4>>>(x, W0, h, n);
    al_kernel<<<(n * 4 + 255) / 256, 256>>>(h, as0, ad0, als, ald, n, 4);
    agg128_kernel<<<gblocks, 256>>>(h, als, ald, b0, gm0, bt0, m0, v0, feat, n);

    // layer 1
    gemm_kernel<128, 128><<<gblocks, 256, 128 * 128 * 4>>>(feat, W1, h, n);
    al_kernel<<<(n * 4 + 255) / 256, 256>>>(h, as1, ad1, als, ald, n, 4);
    agg128_kernel<<<gblocks, 256>>>(h, als, ald, b1, gm1, bt1, m1, v1, feat, n);

    // layer 2 (single head) + classifier
    gemm_kernel<128, 32><<<gblocks, 256, 128 * 32 * 4>>>(feat, W2, h, n);
    al_kernel<<<(n + 255) / 256, 256>>>(h, as2, ad2, als, ald, n, 1);
    agg32_kernel<<<gblocks, 256>>>(h, als, ald, b2, gm2, bt2, m2, v2, Wc, bc,
                                   (float*)d_out, n);
}

// round 2
// speedup vs baseline: 2.2388x; 2.2388x over previous
#include <cuda_runtime.h>
#include <math.h>

#define NNODES 100000
#define NEDGES 1600000

// ---------------- scratch (device globals) ----------------
__device__ __align__(128) float g_feat[NNODES * 128];
__device__ __align__(128) float g_h[NNODES * 128];
__device__ float g_als[NNODES * 4];
__device__ float g_ald[NNODES * 4];
__device__ int   g_deg[NNODES];
__device__ int   g_off[NNODES + 1];
__device__ int   g_cur[NNODES];
__device__ int   g_bsum[128];
__device__ int   g_csr[NEDGES];

// ---------------- CSR build ----------------
__global__ void zero_deg_kernel(int n) {
    int i = blockIdx.x * blockDim.x + threadIdx.x;
    if (i < n) g_deg[i] = 0;
}

__global__ void count_kernel(const int* __restrict__ ei, int e) {
    int i = blockIdx.x * blockDim.x + threadIdx.x;
    if (i < e) atomicAdd(&g_deg[ei[e + i]], 1);
}

__global__ void scan1_kernel(int n) {
    __shared__ int sm[1024];
    int i = blockIdx.x * 1024 + threadIdx.x;
    int v = (i < n) ? g_deg[i] : 0;
    sm[threadIdx.x] = v;
    __syncthreads();
    #pragma unroll
    for (int d = 1; d < 1024; d <<= 1) {
        int t = (threadIdx.x >= d) ? sm[threadIdx.x - d] : 0;
        __syncthreads();
        sm[threadIdx.x] += t;
        __syncthreads();
    }
    if (i < n) g_off[i] = sm[threadIdx.x] - v;   // exclusive within block
    if (threadIdx.x == 1023) g_bsum[blockIdx.x] = sm[1023];
}

// parallel exclusive scan of block sums (nb <= 128)
__global__ void scan2_kernel(int nb) {
    __shared__ int sm[128];
    int t = threadIdx.x;
    int v = (t < nb) ? g_bsum[t] : 0;
    sm[t] = v;
    __syncthreads();
    #pragma unroll
    for (int d = 1; d < 128; d <<= 1) {
        int tv = (t >= d) ? sm[t - d] : 0;
        __syncthreads();
        sm[t] += tv;
        __syncthreads();
    }
    if (t < nb) g_bsum[t] = sm[t] - v;
}

__global__ void scan3_kernel(int n, int e) {
    int i = blockIdx.x * 1024 + threadIdx.x;
    if (i < n) {
        int o = g_off[i] + g_bsum[blockIdx.x];
        g_off[i] = o;
        g_cur[i] = o;
    }
    if (i == 0) g_off[n] = e;
}

__global__ void fill_kernel(const int* __restrict__ ei, int e) {
    int i = blockIdx.x * blockDim.x + threadIdx.x;
    if (i < e) {
        int src = ei[i];
        int dst = ei[e + i];
        int pos = atomicAdd(&g_cur[dst], 1);
        g_csr[pos] = src;
    }
}

// ---------------- GEMM 128->128 + fused attention logits ----------------
// Block 256 threads = 8 warps, 64 rows/block. Warp w owns rows base+w*8..+8;
// lane owns 4 consecutive output cols. 32 acc regs/thread; A tile + W in smem.
__global__ __launch_bounds__(256) void gemm128_kernel(
    const float4* __restrict__ A4, const float* __restrict__ W,
    const float* __restrict__ asrc, const float* __restrict__ adst,
    float4* __restrict__ H4, float* __restrict__ als, float* __restrict__ ald, int n)
{
    extern __shared__ float4 sm4[];
    float4* Wsm4 = sm4;           // 4096 float4 = 64KB (W: [128k][128c])
    float4* Asm4 = sm4 + 4096;    // 2048 float4 = 32KB (A tile: 64 rows x 128)
    int tid = threadIdx.x;
    const float4* W4 = (const float4*)W;
    #pragma unroll 4
    for (int i = tid; i < 4096; i += 256) Wsm4[i] = W4[i];
    int rowbase = blockIdx.x * 64;
    #pragma unroll 2
    for (int i = tid; i < 2048; i += 256) {
        int row = rowbase + (i >> 5);
        Asm4[i] = (row < n) ? A4[(size_t)row * 32 + (i & 31)]
                            : make_float4(0.f, 0.f, 0.f, 0.f);
    }
    __syncthreads();

    int w = tid >> 5, lane = tid & 31;
    float4 acc[8];
    #pragma unroll
    for (int r = 0; r < 8; r++) acc[r] = make_float4(0.f, 0.f, 0.f, 0.f);

    #pragma unroll 4
    for (int k4 = 0; k4 < 32; k4++) {
        float4 w0 = Wsm4[(k4 * 4 + 0) * 32 + lane];
        float4 w1 = Wsm4[(k4 * 4 + 1) * 32 + lane];
        float4 w2 = Wsm4[(k4 * 4 + 2) * 32 + lane];
        float4 w3 = Wsm4[(k4 * 4 + 3) * 32 + lane];
        #pragma unroll
        for (int r = 0; r < 8; r++) {
            float4 a = Asm4[(w * 8 + r) * 32 + k4];
            acc[r].x += a.x * w0.x + a.y * w1.x + a.z * w2.x + a.w * w3.x;
            acc[r].y += a.x * w0.y + a.y * w1.y + a.z * w2.y + a.w * w3.y;
            acc[r].z += a.x * w0.z + a.y * w1.z + a.z * w2.z + a.w * w3.z;
            acc[r].w += a.x * w0.w + a.y * w1.w + a.z * w2.w + a.w * w3.w;
        }
    }

    // epilogue: store H, compute als/ald per (row, head). head = lane>>3.
    float4 asv = ((const float4*)asrc)[lane];   // as flat[col], col = lane*4..
    float4 adv = ((const float4*)adst)[lane];
    int head = lane >> 3;
    #pragma unroll
    for (int r = 0; r < 8; r++) {
        int row = rowbase + w * 8 + r;
        if (row >= n) break;
        H4[(size_t)row * 32 + lane] = acc[r];
        float ps = acc[r].x * asv.x + acc[r].y * asv.y + acc[r].z * asv.z + acc[r].w * asv.w;
        float pd = acc[r].x * adv.x + acc[r].y * adv.y + acc[r].z * adv.z + acc[r].w * adv.w;
        #pragma unroll
        for (int o = 1; o < 8; o <<= 1) {
            ps += __shfl_xor_sync(0xffffffffu, ps, o);
            pd += __shfl_xor_sync(0xffffffffu, pd, o);
        }
        if ((lane & 7) == 0) {
            als[row * 4 + head] = ps;
            ald[row * 4 + head] = pd;
        }
    }
}

// ---------------- GEMM 128->32 + fused attention logits (1 head) ----------------
__global__ __launch_bounds__(256) void gemm32_kernel(
    const float4* __restrict__ A4, const float* __restrict__ W,
    const float* __restrict__ asrc, const float* __restrict__ adst,
    float* __restrict__ H, float* __restrict__ als, float* __restrict__ ald, int n)
{
    __shared__ float  Wsm[128 * 32];    // 16KB
    __shared__ float4 Asm4[2048];       // 32KB
    int tid = threadIdx.x;
    #pragma unroll 4
    for (int i = tid; i < 4096; i += 256) Wsm[i] = W[i];
    int rowbase = blockIdx.x * 64;
    #pragma unroll 2
    for (int i = tid; i < 2048; i += 256) {
        int row = rowbase + (i >> 5);
        Asm4[i] = (row < n) ? A4[(size_t)row * 32 + (i & 31)]
                            : make_float4(0.f, 0.f, 0.f, 0.f);
    }
    __syncthreads();

    int w = tid >> 5, lane = tid & 31;
    float acc[8] = {0.f, 0.f, 0.f, 0.f, 0.f, 0.f, 0.f, 0.f};
    #pragma unroll 4
    for (int k4 = 0; k4 < 32; k4++) {
        float w0 = Wsm[(k4 * 4 + 0) * 32 + lane];
        float w1 = Wsm[(k4 * 4 + 1) * 32 + lane];
        float w2 = Wsm[(k4 * 4 + 2) * 32 + lane];
        float w3 = Wsm[(k4 * 4 + 3) * 32 + lane];
        #pragma unroll
        for (int r = 0; r < 8; r++) {
            float4 a = Asm4[(w * 8 + r) * 32 + k4];
            acc[r] += a.x * w0 + a.y * w1 + a.z * w2 + a.w * w3;
        }
    }

    float asl = asrc[lane], adl = adst[lane];
    #pragma unroll
    for (int r = 0; r < 8; r++) {
        int row = rowbase + w * 8 + r;
        if (row >= n) break;
        H[(size_t)row * 32 + lane] = acc[r];
        float ps = acc[r] * asl;
        float pd = acc[r] * adl;
        #pragma unroll
        for (int o = 1; o < 32; o <<= 1) {
            ps += __shfl_xor_sync(0xffffffffu, ps, o);
            pd += __shfl_xor_sync(0xffffffffu, pd, o);
        }
        if (lane == 0) { als[row] = ps; ald[row] = pd; }
    }
}

// ---------------- aggregation 4 heads x 32ch: no-max softmax + bias + BN + ELU --------
__global__ __launch_bounds__(256) void agg128_kernel(
    const float4* __restrict__ H4, const float* __restrict__ als,
    const float* __restrict__ ald,
    const float* __restrict__ bias, const float* __restrict__ gamma,
    const float* __restrict__ beta, const float* __restrict__ mean,
    const float* __restrict__ var,
    float4* __restrict__ out4, int n)
{
    int v = (blockIdx.x * blockDim.x + threadIdx.x) >> 5;
    if (v >= n) return;
    int lane = threadIdx.x & 31;
    int head = lane >> 3;
    float aldv = __ldg(&ald[v * 4 + head]);
    int s0 = g_off[v], s1 = g_off[v + 1];
    float s = 0.f;
    float4 acc = make_float4(0.f, 0.f, 0.f, 0.f);
    for (int idx = s0; idx < s1; idx++) {
        int u = __ldg(&g_csr[idx]);
        float ee = __ldg(&als[u * 4 + head]) + aldv;
        ee = ee > 0.f ? ee : 0.2f * ee;            // leaky relu
        float wt = __expf(ee);                      // no-max softmax (logits small)
        float4 hv = __ldg(&H4[(size_t)u * 32 + lane]);
        s += wt;
        acc.x += wt * hv.x;
        acc.y += wt * hv.y;
        acc.z += wt * hv.z;
        acc.w += wt * hv.w;
    }
    float inv = 1.f / (s + 1e-16f);
    int c = lane * 4;
    float4 bi = ((const float4*)bias)[lane];
    float4 mn = ((const float4*)mean)[lane];
    float4 vr = ((const float4*)var)[lane];
    float4 gm = ((const float4*)gamma)[lane];
    float4 bt = ((const float4*)beta)[lane];
    float4 y;
    y.x = (acc.x * inv + bi.x - mn.x) * rsqrtf(vr.x + 1e-5f) * gm.x + bt.x;
    y.y = (acc.y * inv + bi.y - mn.y) * rsqrtf(vr.y + 1e-5f) * gm.y + bt.y;
    y.z = (acc.z * inv + bi.z - mn.z) * rsqrtf(vr.z + 1e-5f) * gm.z + bt.z;
    y.w = (acc.w * inv + bi.w - mn.w) * rsqrtf(vr.w + 1e-5f) * gm.w + bt.w;
    y.x = y.x > 0.f ? y.x : expm1f(y.x);
    y.y = y.y > 0.f ? y.y : expm1f(y.y);
    y.z = y.z > 0.f ? y.z : expm1f(y.z);
    y.w = y.w > 0.f ? y.w : expm1f(y.w);
    (void)c;
    out4[(size_t)v * 32 + lane] = y;
}

// ---------------- layer-2 aggregation (1 head) + BN + ELU + classifier ----------------
__global__ __launch_bounds__(256) void agg32_kernel(
    const float* __restrict__ H, const float* __restrict__ als,
    const float* __restrict__ ald,
    const float* __restrict__ bias, const float* __restrict__ gamma,
    const float* __restrict__ beta, const float* __restrict__ mean,
    const float* __restrict__ var,
    const float* __restrict__ Wc, const float* __restrict__ bc,
    float* __restrict__ out, int n)
{
    int v = (blockIdx.x * blockDim.x + threadIdx.x) >> 5;
    if (v >= n) return;
    int lane = threadIdx.x & 31;
    float aldv = __ldg(&ald[v]);
    int s0 = g_off[v], s1 = g_off[v + 1];
    float s = 0.f, acc = 0.f;
    for (int idx = s0; idx < s1; idx++) {
        int u = __ldg(&g_csr[idx]);
        float ee = __ldg(&als[u]) + aldv;
        ee = ee > 0.f ? ee : 0.2f * ee;
        float wt = __expf(ee);
        s += wt;
        acc += wt * __ldg(&H[(size_t)u * 32 + lane]);
    }
    float y = acc / (s + 1e-16f) + bias[lane];
    y = (y - mean[lane]) * rsqrtf(var[lane] + 1e-5f) * gamma[lane] + beta[lane];
    y = y > 0.f ? y : expm1f(y);
    #pragma unroll
    for (int cc = 0; cc < 10; cc++) {
        float p = y * Wc[lane * 10 + cc];
        #pragma unroll
        for (int o = 16; o; o >>= 1) p += __shfl_xor_sync(0xffffffffu, p, o);
        if (lane == 0) out[(size_t)v * 10 + cc] = p + bc[cc];
    }
}

// ---------------- launch ----------------
extern "C" void kernel_launch(void* const* d_in, const int* in_sizes, int n_in,
                              void* d_out, int out_size) {
    const float* x   = (const float*)d_in[0];
    const int*   ei  = (const int*)d_in[1];
    const float* W0  = (const float*)d_in[2];
    const float* as0 = (const float*)d_in[3];
    const float* ad0 = (const float*)d_in[4];
    const float* b0  = (const float*)d_in[5];
    const float* gm0 = (const float*)d_in[6];
    const float* bt0 = (const float*)d_in[7];
    const float* m0  = (const float*)d_in[8];
    const float* v0  = (const float*)d_in[9];
    const float* W1  = (const float*)d_in[10];
    const float* as1 = (const float*)d_in[11];
    const float* ad1 = (const float*)d_in[12];
    const float* b1  = (const float*)d_in[13];
    const float* gm1 = (const float*)d_in[14];
    const float* bt1 = (const float*)d_in[15];
    const float* m1  = (const float*)d_in[16];
    const float* v1  = (const float*)d_in[17];
    const float* W2  = (const float*)d_in[18];
    const float* as2 = (const float*)d_in[19];
    const float* ad2 = (const float*)d_in[20];
    const float* b2  = (const float*)d_in[21];
    const float* gm2 = (const float*)d_in[22];
    const float* bt2 = (const float*)d_in[23];
    const float* m2  = (const float*)d_in[24];
    const float* v2  = (const float*)d_in[25];
    const float* Wc  = (const float*)d_in[26];
    const float* bc  = (const float*)d_in[27];

    int n = in_sizes[0] / 128;   // 100000
    int e = in_sizes[1] / 2;     // 1600000

    float *feat, *h, *als, *ald;
    cudaGetSymbolAddress((void**)&feat, g_feat);
    cudaGetSymbolAddress((void**)&h, g_h);
    cudaGetSymbolAddress((void**)&als, g_als);
    cudaGetSymbolAddress((void**)&ald, g_ald);

    cudaFuncSetAttribute(gemm128_kernel,
                         cudaFuncAttributeMaxDynamicSharedMemorySize, 96 * 1024);

    int nb = (n + 1023) / 1024;
    int eb = (e + 255) / 256;
    int gemm_blocks = (n + 63) / 64;
    int agg_blocks = (n + 7) / 8;

    // CSR by destination (shared by all 3 layers)
    zero_deg_kernel<<<(n + 255) / 256, 256>>>(n);
    count_kernel<<<eb, 256>>>(ei, e);
    scan1_kernel<<<nb, 1024>>>(n);
    scan2_kernel<<<1, 128>>>(nb);
    scan3_kernel<<<nb, 1024>>>(n, e);
    fill_kernel<<<eb, 256>>>(ei, e);

    // layer 0
    gemm128_kernel<<<gemm_blocks, 256, 96 * 1024>>>(
        (const float4*)x, W0, as0, ad0, (float4*)h, als, ald, n);
    agg128_kernel<<<agg_blocks, 256>>>(
        (const float4*)h, als, ald, b0, gm0, bt0, m0, v0, (float4*)feat, n);

    // layer 1
    gemm128_kernel<<<gemm_blocks, 256, 96 * 1024>>>(
        (const float4*)feat, W1, as1, ad1, (float4*)h, als, ald, n);
    agg128_kernel<<<agg_blocks, 256>>>(
        (const float4*)h, als, ald, b1, gm1, bt1, m1, v1, (float4*)feat, n);

    // layer 2 (single head) + classifier
    gemm32_kernel<<<gemm_blocks, 256>>>(
        (const float4*)feat, W2, as2, ad2, h, als, ald, n);
    agg32_kernel<<<agg_blocks, 256>>>(
        h, als, ald, b2, gm2, bt2, m2, v2, Wc, bc, (float*)d_out, n);
}